// round 2
// baseline (speedup 1.0000x reference)
#include <cuda_runtime.h>

#define NN 100000
#define NE 1600000
#define C  128
#define NB 98  // ceil(NN/1024)

// ---------------- device scratch (no allocations allowed) ----------------
__device__ int   g_deg[NN];
__device__ int   g_off[NN + 1];
__device__ int   g_cursor[NN];
__device__ int   g_bsums[NB];
__device__ int   g_csr[NE];
__device__ int   g_is64;          // 1 if edge_index is int64, 0 if int32
__device__ float g_mean[(size_t)NN * C];
__device__ float g_h[(size_t)NN * C];

// Fetch edge value e (0..2*NE-1) honoring dtype flag.
__device__ __forceinline__ int edge_at(const void* ei, int idx) {
    if (g_is64) return (int)((const long long*)ei)[idx];
    return ((const int*)ei)[idx];
}

// ---------------- dtype detection (device-side, graph-safe) ----------------
__global__ void detect_dtype_k(const void* ei) {
    if (threadIdx.x == 0 && blockIdx.x == 0) {
        const int* w = (const int*)ei;
        int all_zero = 1;
        #pragma unroll 1
        for (int i = 0; i < 64; i++) {
            if (w[2 * i + 1] != 0) { all_zero = 0; break; }
        }
        g_is64 = all_zero;   // int64 little-endian: high words of small values are 0
    }
}

// ---------------- CSR construction ----------------
__global__ void zero_deg_k() {
    int i = blockIdx.x * blockDim.x + threadIdx.x;
    if (i < NN) g_deg[i] = 0;
}

__global__ void hist_k(const void* __restrict__ ei) {
    int e = blockIdx.x * blockDim.x + threadIdx.x;
    if (e < NE) {
        int dst = edge_at(ei, NE + e);
        atomicAdd(&g_deg[dst], 1);
    }
}

__global__ void scan1_k() {
    __shared__ int s[1024];
    int i = blockIdx.x * 1024 + threadIdx.x;
    int v = (i < NN) ? g_deg[i] : 0;
    s[threadIdx.x] = v;
    __syncthreads();
    for (int d = 1; d < 1024; d <<= 1) {
        int t = (threadIdx.x >= d) ? s[threadIdx.x - d] : 0;
        __syncthreads();
        s[threadIdx.x] += t;
        __syncthreads();
    }
    if (i < NN) g_off[i] = s[threadIdx.x] - v;   // exclusive
    if (threadIdx.x == 1023) g_bsums[blockIdx.x] = s[1023];
}

__global__ void scan2_k() {
    if (threadIdx.x == 0 && blockIdx.x == 0) {
        int acc = 0;
        for (int b = 0; b < NB; b++) { int t = g_bsums[b]; g_bsums[b] = acc; acc += t; }
    }
}

__global__ void scan3_k() {
    int i = blockIdx.x * 1024 + threadIdx.x;
    if (i < NN) {
        int o = g_off[i] + g_bsums[blockIdx.x];
        g_off[i] = o;
        g_cursor[i] = o;
    }
    if (i == 0) g_off[NN] = NE;
}

__global__ void csr_fill_k(const void* __restrict__ ei) {
    int e = blockIdx.x * blockDim.x + threadIdx.x;
    if (e < NE) {
        int src = edge_at(ei, e);
        int dst = edge_at(ei, NE + e);
        int pos = atomicAdd(&g_cursor[dst], 1);
        g_csr[pos] = src;
    }
}

// ---------------- mean aggregation: one warp per node ----------------
__global__ void __launch_bounds__(256) aggregate_k(const float* __restrict__ xin,
                                                   float* __restrict__ outp) {
    int warp = (blockIdx.x * blockDim.x + threadIdx.x) >> 5;
    int lane = threadIdx.x & 31;
    if (warp >= NN) return;
    int start = g_off[warp];
    int end   = g_off[warp + 1];
    const float4* xv = (const float4*)xin;
    float4 acc = make_float4(0.f, 0.f, 0.f, 0.f);
    int k = start;
    for (; k + 4 <= end; k += 4) {
        int s0 = g_csr[k + 0];
        int s1 = g_csr[k + 1];
        int s2 = g_csr[k + 2];
        int s3 = g_csr[k + 3];
        float4 v0 = xv[(size_t)s0 * 32 + lane];
        float4 v1 = xv[(size_t)s1 * 32 + lane];
        float4 v2 = xv[(size_t)s2 * 32 + lane];
        float4 v3 = xv[(size_t)s3 * 32 + lane];
        acc.x += v0.x + v1.x + v2.x + v3.x;
        acc.y += v0.y + v1.y + v2.y + v3.y;
        acc.z += v0.z + v1.z + v2.z + v3.z;
        acc.w += v0.w + v1.w + v2.w + v3.w;
    }
    for (; k < end; k++) {
        int s = g_csr[k];
        float4 v = xv[(size_t)s * 32 + lane];
        acc.x += v.x; acc.y += v.y; acc.z += v.z; acc.w += v.w;
    }
    int deg = end - start;
    float inv = 1.0f / (float)(deg > 0 ? deg : 1);
    acc.x *= inv; acc.y *= inv; acc.z *= inv; acc.w *= inv;
    ((float4*)outp)[(size_t)warp * 32 + lane] = acc;
}

// ---------------- fused dual GEMM + bias (+relu) ----------------
// out[i][c] = (relu)( sum_k A1[i][k]*Wl[c][k] + sum_k A2[i][k]*Wr[c][k] + bias[c] )
// Block tile: 32 nodes x 128 cols; K=256 virtual (A1/Wl for k<128, A2/Wr after).
template <bool RELU>
__global__ void __launch_bounds__(256) gemm_fused_k(
    const float* __restrict__ A1,   // mean  [NN, C]
    const float* __restrict__ A2,   // x / h [NN, C]
    const float* __restrict__ Wl,   // [C, C]
    const float* __restrict__ Wr,   // [C, C]
    const float* __restrict__ bias, // [C]
    float* __restrict__ outp)       // [NN, C]
{
    __shared__ float As[32][32];    // [node][k]
    __shared__ float Ws[32][128];   // [k][col] (transposed)

    int tid = threadIdx.x;
    int tx  = tid & 31;   // col group: cols tx*4 .. tx*4+3
    int ty  = tid >> 5;   // node group: nodes ty*4 .. ty*4+3
    int nodeBase = blockIdx.x * 32;

    int lnode = tid >> 3;  // 0..31 (loading row)
    int kq    = tid & 7;   // 0..7  (loading k-quad)

    float acc[4][4] = {};

    #pragma unroll 1
    for (int p = 0; p < 8; p++) {
        int k0 = p * 32;
        const float* A = (k0 < C) ? A1 : A2;
        const float* W = (k0 < C) ? Wl : Wr;
        int ko = k0 & (C - 1);

        // stage A tile (float4 coalesced, conflict-free vec4 smem store)
        float4 av = *(const float4*)&A[(size_t)(nodeBase + lnode) * C + ko + kq * 4];
        *(float4*)&As[lnode][kq * 4] = av;

        // stage W tile transposed: Ws[k][c]
        #pragma unroll
        for (int r = 0; r < 4; r++) {
            int c = lnode + 32 * r;
            float4 wv = *(const float4*)&W[(size_t)c * C + ko + kq * 4];
            Ws[kq * 4 + 0][c] = wv.x;
            Ws[kq * 4 + 1][c] = wv.y;
            Ws[kq * 4 + 2][c] = wv.z;
            Ws[kq * 4 + 3][c] = wv.w;
        }
        __syncthreads();

        #pragma unroll
        for (int k = 0; k < 32; k++) {
            float4 b4 = *(const float4*)&Ws[k][tx * 4];
            #pragma unroll
            for (int j = 0; j < 4; j++) {
                float a = As[ty * 4 + j][k];
                acc[j][0] += a * b4.x;
                acc[j][1] += a * b4.y;
                acc[j][2] += a * b4.z;
                acc[j][3] += a * b4.w;
            }
        }
        __syncthreads();
    }

    float4 bb = *(const float4*)&bias[tx * 4];
    #pragma unroll
    for (int j = 0; j < 4; j++) {
        int node = nodeBase + ty * 4 + j;   // 32 | 100000 -> no guard needed
        float4 o;
        o.x = acc[j][0] + bb.x;
        o.y = acc[j][1] + bb.y;
        o.z = acc[j][2] + bb.z;
        o.w = acc[j][3] + bb.w;
        if (RELU) {
            o.x = fmaxf(o.x, 0.f); o.y = fmaxf(o.y, 0.f);
            o.z = fmaxf(o.z, 0.f); o.w = fmaxf(o.w, 0.f);
        }
        *(float4*)&outp[(size_t)node * C + tx * 4] = o;
    }
}

// ---------------- launch ----------------
extern "C" void kernel_launch(void* const* d_in, const int* in_sizes, int n_in,
                              void* d_out, int out_size) {
    const float* x   = (const float*)d_in[0];
    const void*  ei  = d_in[1];                  // int32 or int64, detected on device
    const float* W1l = (const float*)d_in[2];
    const float* b1  = (const float*)d_in[3];
    const float* W1r = (const float*)d_in[4];
    const float* W2l = (const float*)d_in[5];
    const float* b2  = (const float*)d_in[6];
    const float* W2r = (const float*)d_in[7];
    float* out = (float*)d_out;

    float *mean, *h;
    cudaGetSymbolAddress((void**)&mean, g_mean);
    cudaGetSymbolAddress((void**)&h,    g_h);

    // CSR build (reused by both layers)
    detect_dtype_k<<<1, 32>>>(ei);
    zero_deg_k<<<(NN + 255) / 256, 256>>>();
    hist_k<<<(NE + 255) / 256, 256>>>(ei);
    scan1_k<<<NB, 1024>>>();
    scan2_k<<<1, 32>>>();
    scan3_k<<<NB, 1024>>>();
    csr_fill_k<<<(NE + 255) / 256, 256>>>(ei);

    // Layer 1
    aggregate_k<<<(NN * 32 + 255) / 256, 256>>>(x, mean);
    gemm_fused_k<true><<<NN / 32, 256>>>(mean, x, W1l, W1r, b1, h);

    // Layer 2
    aggregate_k<<<(NN * 32 + 255) / 256, 256>>>(h, mean);
    gemm_fused_k<false><<<NN / 32, 256>>>(mean, h, W2l, W2r, b2, out);
}

// round 4
// speedup vs baseline: 2.3147x; 2.3147x over previous
#include <cuda_runtime.h>
#include <cstdint>

#define NN 100000
#define NE 1600000
#define C  128
#define NB 98  // ceil(NN/1024)

// ---------------- device scratch (no allocations allowed) ----------------
__device__ int   g_deg[NN];
__device__ int   g_off[NN + 1];
__device__ int   g_cursor[NN];
__device__ int   g_bsums[NB];
__device__ int   g_csr[NE];
__device__ int   g_is64;          // 1 if edge_index is int64, 0 if int32
__device__ float g_mean[(size_t)NN * C];
__device__ float g_h[(size_t)NN * C];

// Fetch edge value e (0..2*NE-1) honoring dtype flag.
__device__ __forceinline__ int edge_at(const void* ei, int idx) {
    if (g_is64) return (int)((const long long*)ei)[idx];
    return ((const int*)ei)[idx];
}

// ---------------- dtype detection (device-side, graph-safe) ----------------
__global__ void detect_dtype_k(const void* ei) {
    if (threadIdx.x == 0 && blockIdx.x == 0) {
        const int* w = (const int*)ei;
        int all_zero = 1;
        #pragma unroll 1
        for (int i = 0; i < 64; i++) {
            if (w[2 * i + 1] != 0) { all_zero = 0; break; }
        }
        g_is64 = all_zero;   // int64 little-endian: high words of small values are 0
    }
}

// ---------------- CSR construction ----------------
__global__ void zero_deg_k() {
    int i = blockIdx.x * blockDim.x + threadIdx.x;
    if (i < NN) g_deg[i] = 0;
}

__global__ void hist_k(const void* __restrict__ ei) {
    int e = blockIdx.x * blockDim.x + threadIdx.x;
    if (e < NE) {
        int dst = edge_at(ei, NE + e);
        atomicAdd(&g_deg[dst], 1);
    }
}

__global__ void scan1_k() {
    __shared__ int s[1024];
    int i = blockIdx.x * 1024 + threadIdx.x;
    int v = (i < NN) ? g_deg[i] : 0;
    s[threadIdx.x] = v;
    __syncthreads();
    for (int d = 1; d < 1024; d <<= 1) {
        int t = (threadIdx.x >= d) ? s[threadIdx.x - d] : 0;
        __syncthreads();
        s[threadIdx.x] += t;
        __syncthreads();
    }
    if (i < NN) g_off[i] = s[threadIdx.x] - v;   // exclusive
    if (threadIdx.x == 1023) g_bsums[blockIdx.x] = s[1023];
}

__global__ void scan2_k() {
    if (threadIdx.x == 0 && blockIdx.x == 0) {
        int acc = 0;
        for (int b = 0; b < NB; b++) { int t = g_bsums[b]; g_bsums[b] = acc; acc += t; }
    }
}

__global__ void scan3_k() {
    int i = blockIdx.x * 1024 + threadIdx.x;
    if (i < NN) {
        int o = g_off[i] + g_bsums[blockIdx.x];
        g_off[i] = o;
        g_cursor[i] = o;
    }
    if (i == 0) g_off[NN] = NE;
}

__global__ void csr_fill_k(const void* __restrict__ ei) {
    int e = blockIdx.x * blockDim.x + threadIdx.x;
    if (e < NE) {
        int src = edge_at(ei, e);
        int dst = edge_at(ei, NE + e);
        int pos = atomicAdd(&g_cursor[dst], 1);
        g_csr[pos] = src;
    }
}

// ---------------- mean aggregation: one warp per node ----------------
__global__ void __launch_bounds__(256) aggregate_k(const float* __restrict__ xin,
                                                   float* __restrict__ outp) {
    int warp = (blockIdx.x * blockDim.x + threadIdx.x) >> 5;
    int lane = threadIdx.x & 31;
    if (warp >= NN) return;
    int start = g_off[warp];
    int end   = g_off[warp + 1];
    const float4* xv = (const float4*)xin;
    float4 acc = make_float4(0.f, 0.f, 0.f, 0.f);
    int k = start;
    for (; k + 4 <= end; k += 4) {
        int s0 = g_csr[k + 0];
        int s1 = g_csr[k + 1];
        int s2 = g_csr[k + 2];
        int s3 = g_csr[k + 3];
        float4 v0 = xv[(size_t)s0 * 32 + lane];
        float4 v1 = xv[(size_t)s1 * 32 + lane];
        float4 v2 = xv[(size_t)s2 * 32 + lane];
        float4 v3 = xv[(size_t)s3 * 32 + lane];
        acc.x += v0.x + v1.x + v2.x + v3.x;
        acc.y += v0.y + v1.y + v2.y + v3.y;
        acc.z += v0.z + v1.z + v2.z + v3.z;
        acc.w += v0.w + v1.w + v2.w + v3.w;
    }
    for (; k < end; k++) {
        int s = g_csr[k];
        float4 v = xv[(size_t)s * 32 + lane];
        acc.x += v.x; acc.y += v.y; acc.z += v.z; acc.w += v.w;
    }
    int deg = end - start;
    float inv = 1.0f / (float)(deg > 0 ? deg : 1);
    acc.x *= inv; acc.y *= inv; acc.z *= inv; acc.w *= inv;
    ((float4*)outp)[(size_t)warp * 32 + lane] = acc;
}

// ---------------- tf32 tensor-core fused dual GEMM + bias (+relu) ----------------
// out[i][c] = (relu)( sum_k A1[i][k]*Wl[c][k] + sum_k A2[i][k]*Wr[c][k] + bias[c] )
// Block: 128 nodes x 128 cols. 8 warps, each 64x32 via 4x4 mma.m16n8k8 tiles.
// K = 256 virtual: first 128 from (A1, Wl), second 128 from (A2, Wr).

__device__ __forceinline__ uint32_t to_tf32(float x) {
    uint32_t r;
    asm("cvt.rna.tf32.f32 %0, %1;" : "=r"(r) : "f"(x));
    return r;
}

#define AS_STRIDE 36  // 32 + 4 pad -> conflict-free fragment reads

template <bool RELU>
__global__ void __launch_bounds__(256) gemm_tc_k(
    const float* __restrict__ A1,   // mean  [NN, C]
    const float* __restrict__ A2,   // x / h [NN, C]
    const float* __restrict__ Wl,   // [C, C]
    const float* __restrict__ Wr,   // [C, C]
    const float* __restrict__ bias, // [C]
    float* __restrict__ outp)       // [NN, C]
{
    __shared__ uint32_t As[128][AS_STRIDE];  // [node][k]   (tf32 bit patterns)
    __shared__ uint32_t Ws[128][AS_STRIDE];  // [outcol][k] (== B col-major for mma)

    const int tid  = threadIdx.x;
    const int lane = tid & 31;
    const int wid  = tid >> 5;
    const int warpRow = wid >> 2;   // 0..1  -> 64-node slab
    const int warpCol = wid & 3;    // 0..3  -> 32-col slab
    const int nodeBase = blockIdx.x * 128;

    const int lr = lane >> 2;       // 0..7
    const int lc = lane & 3;        // 0..3

    float acc[4][4][4] = {};        // [m-tile][n-tile][frag]

    #pragma unroll 1
    for (int half = 0; half < 2; half++) {
        const float* A = half ? A2 : A1;
        const float* W = half ? Wr : Wl;
        #pragma unroll 1
        for (int chunk = 0; chunk < 4; chunk++) {
            const int kOff = chunk * 32;
            // ---- stage A tile (128 x 32) and W tile (128 x 32), tf32-rounded ----
            #pragma unroll
            for (int t = 0; t < 4; t++) {
                int idx = tid + t * 256;        // 0..1023
                int row = idx >> 3;             // 0..127
                int q   = idx & 7;              // float4 quad
                int gnode = nodeBase + row;
                float4 av = (gnode < NN)
                    ? *(const float4*)&A[(size_t)gnode * C + kOff + q * 4]
                    : make_float4(0.f, 0.f, 0.f, 0.f);
                As[row][q * 4 + 0] = to_tf32(av.x);
                As[row][q * 4 + 1] = to_tf32(av.y);
                As[row][q * 4 + 2] = to_tf32(av.z);
                As[row][q * 4 + 3] = to_tf32(av.w);
                float4 wv = *(const float4*)&W[(size_t)row * C + kOff + q * 4];
                Ws[row][q * 4 + 0] = to_tf32(wv.x);
                Ws[row][q * 4 + 1] = to_tf32(wv.y);
                Ws[row][q * 4 + 2] = to_tf32(wv.z);
                Ws[row][q * 4 + 3] = to_tf32(wv.w);
            }
            __syncthreads();

            // ---- 4 k8-steps over this 32-k chunk ----
            #pragma unroll
            for (int ks = 0; ks < 4; ks++) {
                const int k0 = ks * 8;
                // B fragments: b0 = W[c][k0+lc], b1 = W[c][k0+lc+4], c = colbase+lr
                uint32_t bf[4][2];
                #pragma unroll
                for (int nt = 0; nt < 4; nt++) {
                    int c = warpCol * 32 + nt * 8 + lr;
                    bf[nt][0] = Ws[c][k0 + lc];
                    bf[nt][1] = Ws[c][k0 + lc + 4];
                }
                #pragma unroll
                for (int mt = 0; mt < 4; mt++) {
                    int r = warpRow * 64 + mt * 16 + lr;
                    uint32_t a0 = As[r][k0 + lc];
                    uint32_t a1 = As[r + 8][k0 + lc];
                    uint32_t a2 = As[r][k0 + lc + 4];
                    uint32_t a3 = As[r + 8][k0 + lc + 4];
                    #pragma unroll
                    for (int nt = 0; nt < 4; nt++) {
                        asm volatile(
                            "mma.sync.aligned.m16n8k8.row.col.f32.tf32.tf32.f32 "
                            "{%0,%1,%2,%3}, {%4,%5,%6,%7}, {%8,%9}, {%0,%1,%2,%3};"
                            : "+f"(acc[mt][nt][0]), "+f"(acc[mt][nt][1]),
                              "+f"(acc[mt][nt][2]), "+f"(acc[mt][nt][3])
                            : "r"(a0), "r"(a1), "r"(a2), "r"(a3),
                              "r"(bf[nt][0]), "r"(bf[nt][1]));
                    }
                }
            }
            __syncthreads();
        }
    }

    // ---- epilogue: bias (+relu), write float2 per fragment row ----
    #pragma unroll
    for (int nt = 0; nt < 4; nt++) {
        int c = warpCol * 32 + nt * 8 + 2 * lc;
        float bb0 = bias[c];
        float bb1 = bias[c + 1];
        #pragma unroll
        for (int mt = 0; mt < 4; mt++) {
            int r0 = nodeBase + warpRow * 64 + mt * 16 + lr;
            int r1 = r0 + 8;
            float o0 = acc[mt][nt][0] + bb0;
            float o1 = acc[mt][nt][1] + bb1;
            float o2 = acc[mt][nt][2] + bb0;
            float o3 = acc[mt][nt][3] + bb1;
            if (RELU) {
                o0 = fmaxf(o0, 0.f); o1 = fmaxf(o1, 0.f);
                o2 = fmaxf(o2, 0.f); o3 = fmaxf(o3, 0.f);
            }
            if (r0 < NN) *(float2*)&outp[(size_t)r0 * C + c] = make_float2(o0, o1);
            if (r1 < NN) *(float2*)&outp[(size_t)r1 * C + c] = make_float2(o2, o3);
        }
    }
}

// ---------------- launch ----------------
extern "C" void kernel_launch(void* const* d_in, const int* in_sizes, int n_in,
                              void* d_out, int out_size) {
    const float* x   = (const float*)d_in[0];
    const void*  ei  = d_in[1];                  // int32 or int64, detected on device
    const float* W1l = (const float*)d_in[2];
    const float* b1  = (const float*)d_in[3];
    const float* W1r = (const float*)d_in[4];
    const float* W2l = (const float*)d_in[5];
    const float* b2  = (const float*)d_in[6];
    const float* W2r = (const float*)d_in[7];
    float* out = (float*)d_out;

    float *mean, *h;
    cudaGetSymbolAddress((void**)&mean, g_mean);
    cudaGetSymbolAddress((void**)&h,    g_h);

    // CSR build (reused by both layers)
    detect_dtype_k<<<1, 32>>>(ei);
    zero_deg_k<<<(NN + 255) / 256, 256>>>();
    hist_k<<<(NE + 255) / 256, 256>>>(ei);
    scan1_k<<<NB, 1024>>>();
    scan2_k<<<1, 32>>>();
    scan3_k<<<NB, 1024>>>();
    csr_fill_k<<<(NE + 255) / 256, 256>>>(ei);

    const int gemmGrid = (NN + 127) / 128;  // 782

    // Layer 1
    aggregate_k<<<(NN * 32 + 255) / 256, 256>>>(x, mean);
    gemm_tc_k<true><<<gemmGrid, 256>>>(mean, x, W1l, W1r, b1, h);

    // Layer 2
    aggregate_k<<<(NN * 32 + 255) / 256, 256>>>(h, mean);
    gemm_tc_k<false><<<gemmGrid, 256>>>(mean, h, W2l, W2r, b2, out);
}